// round 1
// baseline (speedup 1.0000x reference)
#include <cuda_runtime.h>

// ---------------------------------------------------------------------------
// KPlaneRBFField on GB300.
// Pass 1: transpose the 9 planes [32, r, r] -> [r, r, 32] into device scratch
//         so that each bilinear corner for all 32 channels is ONE 128B line.
// Pass 2: one warp per point, lane = channel. 9 bilinear samples (product of 3
//         planes per scale) + 8-corner RBF over lc0 (rows already contiguous),
//         + kpb bias; 128 floats out per point (4 coalesced 128B stores).
// ---------------------------------------------------------------------------

#define NSIDE 64
#define LCDIM 32

// Transposed plane scratch:
// scale0 (r=128): 3 * 128*128*32 = 1,572,864 floats
// scale1 (r=256): 3 * 256*256*32 = 6,291,456 floats
// scale2 (r=512): 3 * 512*512*32 = 25,165,824 floats
// total = 33,030,144 floats (132 MB)
__device__ float g_planesT[33030144];

__constant__ long c_plane_off[9] = {
    0L,        524288L,   1048576L,      // scale0
    1572864L,  3670016L,  5767168L,      // scale1
    7864320L,  16252928L, 24641536L      // scale2
};

// --------------------------- transpose kernel -------------------------------
// src: [32, rr] (channel-major), dst (g_planesT + off): [rr, 32]
__global__ void __launch_bounds__(256) transpose_plane_kernel(
    const float* __restrict__ src, int rr, long dstOff)
{
    __shared__ float tile[32][33];
    float* dst = g_planesT + dstOff;
    int posBase = blockIdx.x * 32;
    int tx = threadIdx.x;           // 0..31
    int ty = threadIdx.y;           // 0..7

    #pragma unroll
    for (int cy = ty; cy < 32; cy += 8)
        tile[tx][cy] = src[(long)cy * rr + posBase + tx];   // coalesced read along pos
    __syncthreads();
    #pragma unroll
    for (int py = ty; py < 32; py += 8)
        dst[(long)(posBase + py) * 32 + tx] = tile[py][tx]; // coalesced write along ch
}

// --------------------------- bilinear sample --------------------------------
__device__ __forceinline__ float bsample(const float* __restrict__ T, int r,
                                         float u, float v, int lane)
{
    float fr = (float)(r - 1);
    float fx = (u + 1.0f) * 0.5f * fr;
    float fy = (v + 1.0f) * 0.5f * fr;
    float flx = floorf(fx);
    float fly = floorf(fy);
    flx = fminf(fmaxf(flx, 0.0f), (float)(r - 2));
    fly = fminf(fmaxf(fly, 0.0f), (float)(r - 2));
    float wx = fx - flx;
    float wy = fy - fly;
    int ix = (int)flx;
    int iy = (int)fly;
    const float* b = T + (((long)(iy * r + ix)) << 5) + lane;
    long rowStep = ((long)r) << 5;
    float v00 = __ldg(b);
    float v01 = __ldg(b + 32);
    float v10 = __ldg(b + rowStep);
    float v11 = __ldg(b + rowStep + 32);
    float top = v00 + (v01 - v00) * wx;
    float bot = v10 + (v11 - v10) * wx;
    return top + (bot - top) * wy;
}

// --------------------------- main field kernel ------------------------------
__global__ void __launch_bounds__(256) field_kernel(
    const float* __restrict__ pts,
    const float* __restrict__ aabb,
    const float* __restrict__ lc0,
    const float* __restrict__ ks,
    const float* __restrict__ kpb,
    float* __restrict__ out,
    int npts)
{
    int warp = (int)((blockIdx.x * (long)blockDim.x + threadIdx.x) >> 5);
    int lane = threadIdx.x & 31;
    if (warp >= npts) return;

    // point coords (warp-uniform loads)
    const float* p = pts + 3L * warp;
    float px = __ldg(&p[0]);
    float py = __ldg(&p[1]);
    float pz = __ldg(&p[2]);

    float a0x = __ldg(&aabb[0]), a0y = __ldg(&aabb[1]), a0z = __ldg(&aabb[2]);
    float a1x = __ldg(&aabb[3]), a1y = __ldg(&aabb[4]), a1z = __ldg(&aabb[5]);

    float xs0 = (px - a0x) * (2.0f / (a1x - a0x)) - 1.0f;
    float xs1 = (py - a0y) * (2.0f / (a1y - a0y)) - 1.0f;
    float xs2 = (pz - a0z) * (2.0f / (a1z - a0z)) - 1.0f;

    long outBase = (long)warp * 128;

    // ---- K-plane features: 3 scales, product over {(0,1),(0,2),(1,2)} planes
    const int resArr[3] = {128, 256, 512};
    #pragma unroll
    for (int s = 0; s < 3; s++) {
        int r = resArr[s];
        const float* T0 = g_planesT + c_plane_off[s * 3 + 0];
        const float* T1 = g_planesT + c_plane_off[s * 3 + 1];
        const float* T2 = g_planesT + c_plane_off[s * 3 + 2];
        float f = bsample(T0, r, xs0, xs1, lane)
                * bsample(T1, r, xs0, xs2, lane)
                * bsample(T2, r, xs1, xs2, lane);
        out[outBase + s * 32 + lane] = f + __ldg(&kpb[s * 32 + lane]);
    }

    // ---- RBF features over 64^3 grid on [-1,1]
    const float interval = 2.0f / (float)(NSIDE - 1);
    float c0 = floorf((xs0 + 1.0f) / interval);
    float c1 = floorf((xs1 + 1.0f) / interval);
    float c2 = floorf((xs2 + 1.0f) / interval);
    c0 = fminf(fmaxf(c0, 0.0f), (float)(NSIDE - 2));
    c1 = fminf(fmaxf(c1, 0.0f), (float)(NSIDE - 2));
    c2 = fminf(fmaxf(c2, 0.0f), (float)(NSIDE - 2));
    int ci0 = (int)c0, ci1 = (int)c1, ci2 = (int)c2;

    float acc = 0.0f;
    float wsum = 0.0f;
    #pragma unroll
    for (int k = 0; k < 8; k++) {
        int i0 = ci0 + ((k >> 2) & 1);
        int i1 = ci1 + ((k >> 1) & 1);
        int i2 = ci2 + (k & 1);
        int idx = (i0 * NSIDE + i1) * NSIDE + i2;
        float k0 = -1.0f + (float)i0 * interval;
        float k1 = -1.0f + (float)i1 * interval;
        float k2 = -1.0f + (float)i2 * interval;
        float d0 = xs0 - k0;
        float d1 = xs1 - k1;
        float d2 = xs2 - k2;
        float dist2 = d0 * d0 + d1 * d1 + d2 * d2;
        float sv = __ldg(&ks[idx]);                 // warp-uniform scalar
        float phi = 1.0f / (1.0f + dist2 * sv * sv);
        wsum += phi;
        acc += phi * __ldg(&lc0[((long)idx << 5) + lane]);  // 128B coalesced row
    }
    out[outBase + 96 + lane] = acc / (wsum + 1e-8f) + __ldg(&kpb[96 + lane]);
}

// ------------------------------ launcher ------------------------------------
extern "C" void kernel_launch(void* const* d_in, const int* in_sizes, int n_in,
                              void* d_out, int out_size)
{
    const float* pts  = (const float*)d_in[0];
    const float* aabb = (const float*)d_in[1];
    // d_in[2..10] = p00 p01 p02 p10 p11 p12 p20 p21 p22
    const float* lc0  = (const float*)d_in[11];
    const float* ks   = (const float*)d_in[12];
    const float* kpb  = (const float*)d_in[13];
    float* out = (float*)d_out;

    int npts = in_sizes[0] / 3;

    const int resArr[3] = {128, 256, 512};
    dim3 tb(32, 8);
    for (int s = 0; s < 3; s++) {
        int rr = resArr[s] * resArr[s];
        for (int c = 0; c < 3; c++) {
            int pi = s * 3 + c;
            long off;
            // mirror c_plane_off on host
            static const long hoff[9] = {0L, 524288L, 1048576L,
                                         1572864L, 3670016L, 5767168L,
                                         7864320L, 16252928L, 24641536L};
            off = hoff[pi];
            transpose_plane_kernel<<<rr / 32, tb>>>((const float*)d_in[2 + pi], rr, off);
        }
    }

    int threads = 256;                       // 8 warps/block, 1 point per warp
    int warpsPerBlock = threads / 32;
    int blocks = (npts + warpsPerBlock - 1) / warpsPerBlock;
    field_kernel<<<blocks, threads>>>(pts, aabb, lc0, ks, kpb, out, npts);
}

// round 2
// speedup vs baseline: 1.1989x; 1.1989x over previous
#include <cuda_runtime.h>

// ---------------------------------------------------------------------------
// KPlaneRBFField on GB300 — round 2.
//  Pass 1: fast float4 transpose of 9 planes [32,r,r] -> [r,r,32] (one 128B
//          line per bilinear corner for all 32 channels).
//  Pass 2: Morton-bucket counting sort of the 524288 points (32^3 cells) so
//          consecutive warps have spatial locality -> compulsory-only DRAM.
//  Pass 3: one warp per point (lane = channel): 9 bilinear samples + 8-corner
//          RBF + bias; 512B coalesced output row per point.
// ---------------------------------------------------------------------------

#define NSIDE 64
#define MAXN  524288
#define NBUCK 32768          // 32^3 Morton buckets

__device__ float    g_planesT[33030144];   // 132 MB transposed planes
__device__ unsigned g_hist[NBUCK];
__device__ unsigned g_key[MAXN];
__device__ int      g_order[MAXN];

__constant__ long c_plane_off[9] = {
    0L,        524288L,   1048576L,      // scale0 (r=128)
    1572864L,  3670016L,  5767168L,      // scale1 (r=256)
    7864320L,  16252928L, 24641536L      // scale2 (r=512)
};

// --------------------------- transpose kernel -------------------------------
// src: [32, rr] channel-major.  dst = g_planesT+off : [rr, 32].
// 128 positions per block; float4 loads and float4 stores.
#define TP_POS 128
__global__ void __launch_bounds__(256) transpose_plane_kernel(
    const float* __restrict__ src, int rr, long dstOff)
{
    __shared__ float tile[TP_POS][33];
    int posBase = blockIdx.x * TP_POS;
    int tid = threadIdx.x;
    const float4* src4 = (const float4*)src;
    int rr4 = rr >> 2;
    int pb4 = posBase >> 2;

    #pragma unroll
    for (int it = 0; it < 4; it++) {
        int v  = tid + it * 256;        // 0..1023
        int ch = v >> 5;                // 0..31
        int pv = v & 31;                // float4 index along pos
        float4 val = src4[(long)ch * rr4 + pb4 + pv];
        int p = pv << 2;
        tile[p + 0][ch] = val.x;
        tile[p + 1][ch] = val.y;
        tile[p + 2][ch] = val.z;
        tile[p + 3][ch] = val.w;
    }
    __syncthreads();

    float4* dst4 = (float4*)(g_planesT + dstOff + (long)posBase * 32);
    #pragma unroll
    for (int it = 0; it < 4; it++) {
        int v  = tid + it * 256;        // 0..1023  (= p*8 + c4)
        int p  = v >> 3;
        int c4 = (v & 7) << 2;
        float4 o;
        o.x = tile[p][c4 + 0];
        o.y = tile[p][c4 + 1];
        o.z = tile[p][c4 + 2];
        o.w = tile[p][c4 + 3];
        dst4[v] = o;
    }
}

// --------------------------- sorting kernels --------------------------------
__device__ __forceinline__ unsigned spread3(unsigned x)
{
    x &= 0x3FF;
    x = (x | (x << 16)) & 0x30000FF;
    x = (x | (x << 8))  & 0x300F00F;
    x = (x | (x << 4))  & 0x30C30C3;
    x = (x | (x << 2))  & 0x9249249;
    return x;
}

__global__ void zero_hist_kernel()
{
    g_hist[blockIdx.x * 256 + threadIdx.x] = 0;
}

__global__ void hist_kernel(const float* __restrict__ pts,
                            const float* __restrict__ aabb, int n)
{
    int i = blockIdx.x * blockDim.x + threadIdx.x;
    if (i >= n) return;
    float a0x = aabb[0], a0y = aabb[1], a0z = aabb[2];
    float a1x = aabb[3], a1y = aabb[4], a1z = aabb[5];
    float x = (pts[3 * i + 0] - a0x) * (2.0f / (a1x - a0x)) - 1.0f;
    float y = (pts[3 * i + 1] - a0y) * (2.0f / (a1y - a0y)) - 1.0f;
    float z = (pts[3 * i + 2] - a0z) * (2.0f / (a1z - a0z)) - 1.0f;
    int qx = min(max((int)((x + 1.0f) * 16.0f), 0), 31);
    int qy = min(max((int)((y + 1.0f) * 16.0f), 0), 31);
    int qz = min(max((int)((z + 1.0f) * 16.0f), 0), 31);
    unsigned key = (spread3(qx) << 2) | (spread3(qy) << 1) | spread3(qz);
    g_key[i] = key;
    atomicAdd(&g_hist[key], 1u);
}

// exclusive scan of g_hist (32768 entries) in one block of 1024 threads
__global__ void __launch_bounds__(1024) scan_kernel()
{
    __shared__ unsigned partial[1024];
    int t = threadIdx.x;
    unsigned vals[32];
    unsigned sum = 0;
    #pragma unroll
    for (int k = 0; k < 32; k++) {
        vals[k] = g_hist[t * 32 + k];
        sum += vals[k];
    }
    partial[t] = sum;
    __syncthreads();
    // Hillis-Steele inclusive scan over the 1024 partials
    #pragma unroll
    for (int off = 1; off < 1024; off <<= 1) {
        unsigned v = (t >= off) ? partial[t - off] : 0u;
        __syncthreads();
        partial[t] += v;
        __syncthreads();
    }
    unsigned run = partial[t] - sum;   // exclusive prefix for this thread's chunk
    #pragma unroll
    for (int k = 0; k < 32; k++) {
        unsigned v = vals[k];
        g_hist[t * 32 + k] = run;
        run += v;
    }
}

__global__ void scatter_kernel(int n)
{
    int i = blockIdx.x * blockDim.x + threadIdx.x;
    if (i >= n) return;
    unsigned pos = atomicAdd(&g_hist[g_key[i]], 1u);
    g_order[pos] = i;
}

// --------------------------- bilinear sample --------------------------------
__device__ __forceinline__ float bsample(const float* __restrict__ T, int r,
                                         float u, float v, int lane)
{
    float fr = (float)(r - 1);
    float fx = (u + 1.0f) * 0.5f * fr;
    float fy = (v + 1.0f) * 0.5f * fr;
    float flx = floorf(fx);
    float fly = floorf(fy);
    flx = fminf(fmaxf(flx, 0.0f), (float)(r - 2));
    fly = fminf(fmaxf(fly, 0.0f), (float)(r - 2));
    float wx = fx - flx;
    float wy = fy - fly;
    int ix = (int)flx;
    int iy = (int)fly;
    const float* b = T + (((long)(iy * r + ix)) << 5) + lane;
    long rowStep = ((long)r) << 5;
    float v00 = __ldg(b);
    float v01 = __ldg(b + 32);
    float v10 = __ldg(b + rowStep);
    float v11 = __ldg(b + rowStep + 32);
    float top = v00 + (v01 - v00) * wx;
    float bot = v10 + (v11 - v10) * wx;
    return top + (bot - top) * wy;
}

// --------------------------- main field kernel ------------------------------
__global__ void __launch_bounds__(256) field_kernel(
    const float* __restrict__ pts,
    const float* __restrict__ aabb,
    const float* __restrict__ lc0,
    const float* __restrict__ ks,
    const float* __restrict__ kpb,
    float* __restrict__ out,
    int npts, int useOrder)
{
    int warp = (int)((blockIdx.x * (long)blockDim.x + threadIdx.x) >> 5);
    int lane = threadIdx.x & 31;
    if (warp >= npts) return;

    int pid = useOrder ? g_order[warp] : warp;

    const float* p = pts + 3L * pid;
    float px = __ldg(&p[0]);
    float py = __ldg(&p[1]);
    float pz = __ldg(&p[2]);

    float a0x = __ldg(&aabb[0]), a0y = __ldg(&aabb[1]), a0z = __ldg(&aabb[2]);
    float a1x = __ldg(&aabb[3]), a1y = __ldg(&aabb[4]), a1z = __ldg(&aabb[5]);

    float xs0 = (px - a0x) * (2.0f / (a1x - a0x)) - 1.0f;
    float xs1 = (py - a0y) * (2.0f / (a1y - a0y)) - 1.0f;
    float xs2 = (pz - a0z) * (2.0f / (a1z - a0z)) - 1.0f;

    long outBase = (long)pid * 128;

    const int resArr[3] = {128, 256, 512};
    #pragma unroll
    for (int s = 0; s < 3; s++) {
        int r = resArr[s];
        const float* T0 = g_planesT + c_plane_off[s * 3 + 0];
        const float* T1 = g_planesT + c_plane_off[s * 3 + 1];
        const float* T2 = g_planesT + c_plane_off[s * 3 + 2];
        float f = bsample(T0, r, xs0, xs1, lane)
                * bsample(T1, r, xs0, xs2, lane)
                * bsample(T2, r, xs1, xs2, lane);
        out[outBase + s * 32 + lane] = f + __ldg(&kpb[s * 32 + lane]);
    }

    // ---- RBF features over 64^3 grid on [-1,1]
    const float interval = 2.0f / (float)(NSIDE - 1);
    float c0 = floorf((xs0 + 1.0f) / interval);
    float c1 = floorf((xs1 + 1.0f) / interval);
    float c2 = floorf((xs2 + 1.0f) / interval);
    c0 = fminf(fmaxf(c0, 0.0f), (float)(NSIDE - 2));
    c1 = fminf(fmaxf(c1, 0.0f), (float)(NSIDE - 2));
    c2 = fminf(fmaxf(c2, 0.0f), (float)(NSIDE - 2));
    int ci0 = (int)c0, ci1 = (int)c1, ci2 = (int)c2;

    float acc = 0.0f;
    float wsum = 0.0f;
    #pragma unroll
    for (int k = 0; k < 8; k++) {
        int i0 = ci0 + ((k >> 2) & 1);
        int i1 = ci1 + ((k >> 1) & 1);
        int i2 = ci2 + (k & 1);
        int idx = (i0 * NSIDE + i1) * NSIDE + i2;
        float k0 = -1.0f + (float)i0 * interval;
        float k1 = -1.0f + (float)i1 * interval;
        float k2 = -1.0f + (float)i2 * interval;
        float d0 = xs0 - k0;
        float d1 = xs1 - k1;
        float d2 = xs2 - k2;
        float dist2 = d0 * d0 + d1 * d1 + d2 * d2;
        float sv = __ldg(&ks[idx]);
        float phi = 1.0f / (1.0f + dist2 * sv * sv);
        wsum += phi;
        acc += phi * __ldg(&lc0[((long)idx << 5) + lane]);
    }
    out[outBase + 96 + lane] = acc / (wsum + 1e-8f) + __ldg(&kpb[96 + lane]);
}

// ------------------------------ launcher ------------------------------------
extern "C" void kernel_launch(void* const* d_in, const int* in_sizes, int n_in,
                              void* d_out, int out_size)
{
    const float* pts  = (const float*)d_in[0];
    const float* aabb = (const float*)d_in[1];
    const float* lc0  = (const float*)d_in[11];
    const float* ks   = (const float*)d_in[12];
    const float* kpb  = (const float*)d_in[13];
    float* out = (float*)d_out;

    int npts = in_sizes[0] / 3;

    static const long hoff[9] = {0L, 524288L, 1048576L,
                                 1572864L, 3670016L, 5767168L,
                                 7864320L, 16252928L, 24641536L};
    const int resArr[3] = {128, 256, 512};
    for (int s = 0; s < 3; s++) {
        int rr = resArr[s] * resArr[s];
        for (int c = 0; c < 3; c++) {
            int pi = s * 3 + c;
            transpose_plane_kernel<<<rr / TP_POS, 256>>>(
                (const float*)d_in[2 + pi], rr, hoff[pi]);
        }
    }

    int useOrder = (npts <= MAXN) ? 1 : 0;
    if (useOrder) {
        zero_hist_kernel<<<NBUCK / 256, 256>>>();
        hist_kernel<<<(npts + 255) / 256, 256>>>(pts, aabb, npts);
        scan_kernel<<<1, 1024>>>();
        scatter_kernel<<<(npts + 255) / 256, 256>>>(npts);
    }

    int threads = 256;                       // 8 warps/block, 1 point per warp
    int warpsPerBlock = threads / 32;
    int blocks = (npts + warpsPerBlock - 1) / warpsPerBlock;
    field_kernel<<<blocks, threads>>>(pts, aabb, lc0, ks, kpb, out, npts, useOrder);
}

// round 3
// speedup vs baseline: 1.8007x; 1.5020x over previous
#include <cuda_runtime.h>

// ---------------------------------------------------------------------------
// KPlaneRBFField on GB300 — round 3.
//  Pass 1: ONE fused transpose kernel for all 9 planes [32,r,r] -> [r,r,32].
//  Pass 2: Morton-bucket counting sort (32^3 cells) for spatial locality.
//  Pass 3: field kernel, 4 points per warp, lane = point*8 + chan_quad,
//          float4 loads/stores -> ~15 warp-LDG per point (was ~58).
// ---------------------------------------------------------------------------

#define NSIDE 64
#define MAXN  524288
#define NBUCK 32768
#define TP_POS 128

__device__ float    g_planesT[33030144];   // 132 MB transposed planes
__device__ unsigned g_hist[NBUCK];
__device__ unsigned g_key[MAXN];
__device__ int      g_order[MAXN];

// per-plane metadata (compile-time geometry)
__constant__ long c_plane_off[9] = {
    0L,        524288L,   1048576L,
    1572864L,  3670016L,  5767168L,
    7864320L,  16252928L, 24641536L
};
// blocks per plane at 128 positions/block: {128,128,128,512,512,512,2048,2048,2048}
__constant__ int c_blkCum[10] = {0,128,256,384,896,1408,1920,3968,6016,8064};
__constant__ int c_res[9]     = {128,128,128,256,256,256,512,512,512};

struct PlanePtrs { const float* p[9]; };

// --------------------------- fused transpose --------------------------------
__global__ void __launch_bounds__(256) transpose_all_kernel(PlanePtrs ptrs)
{
    __shared__ float tile[TP_POS][33];
    int b = blockIdx.x;
    int pi = 0;
    #pragma unroll
    for (int i = 1; i < 9; i++) pi += (b >= c_blkCum[i]) ? 1 : 0;
    int r  = c_res[pi];
    int rr = r * r;
    int posBase = (b - c_blkCum[pi]) * TP_POS;
    const float* src = ptrs.p[pi];

    int tid = threadIdx.x;
    const float4* src4 = (const float4*)src;
    int rr4 = rr >> 2;
    int pb4 = posBase >> 2;

    #pragma unroll
    for (int it = 0; it < 4; it++) {
        int v  = tid + it * 256;        // 0..1023
        int ch = v >> 5;                // 0..31
        int pv = v & 31;                // float4 index along pos
        float4 val = src4[(long)ch * rr4 + pb4 + pv];
        int p = pv << 2;
        tile[p + 0][ch] = val.x;
        tile[p + 1][ch] = val.y;
        tile[p + 2][ch] = val.z;
        tile[p + 3][ch] = val.w;
    }
    __syncthreads();

    float4* dst4 = (float4*)(g_planesT + c_plane_off[pi] + (long)posBase * 32);
    #pragma unroll
    for (int it = 0; it < 4; it++) {
        int v  = tid + it * 256;        // = p*8 + c4
        int p  = v >> 3;
        int c4 = (v & 7) << 2;
        float4 o;
        o.x = tile[p][c4 + 0];
        o.y = tile[p][c4 + 1];
        o.z = tile[p][c4 + 2];
        o.w = tile[p][c4 + 3];
        dst4[v] = o;
    }
}

// --------------------------- sorting kernels --------------------------------
__device__ __forceinline__ unsigned spread3(unsigned x)
{
    x &= 0x3FF;
    x = (x | (x << 16)) & 0x30000FF;
    x = (x | (x << 8))  & 0x300F00F;
    x = (x | (x << 4))  & 0x30C30C3;
    x = (x | (x << 2))  & 0x9249249;
    return x;
}

__global__ void zero_hist_kernel()
{
    g_hist[blockIdx.x * 256 + threadIdx.x] = 0;
}

__global__ void hist_kernel(const float* __restrict__ pts,
                            const float* __restrict__ aabb, int n)
{
    int i = blockIdx.x * blockDim.x + threadIdx.x;
    if (i >= n) return;
    float a0x = aabb[0], a0y = aabb[1], a0z = aabb[2];
    float a1x = aabb[3], a1y = aabb[4], a1z = aabb[5];
    float x = (pts[3 * i + 0] - a0x) * (2.0f / (a1x - a0x)) - 1.0f;
    float y = (pts[3 * i + 1] - a0y) * (2.0f / (a1y - a0y)) - 1.0f;
    float z = (pts[3 * i + 2] - a0z) * (2.0f / (a1z - a0z)) - 1.0f;
    int qx = min(max((int)((x + 1.0f) * 16.0f), 0), 31);
    int qy = min(max((int)((y + 1.0f) * 16.0f), 0), 31);
    int qz = min(max((int)((z + 1.0f) * 16.0f), 0), 31);
    unsigned key = (spread3(qx) << 2) | (spread3(qy) << 1) | spread3(qz);
    g_key[i] = key;
    atomicAdd(&g_hist[key], 1u);
}

__global__ void __launch_bounds__(1024) scan_kernel()
{
    __shared__ unsigned partial[1024];
    int t = threadIdx.x;
    unsigned vals[32];
    unsigned sum = 0;
    #pragma unroll
    for (int k = 0; k < 32; k++) {
        vals[k] = g_hist[t * 32 + k];
        sum += vals[k];
    }
    partial[t] = sum;
    __syncthreads();
    #pragma unroll
    for (int off = 1; off < 1024; off <<= 1) {
        unsigned v = (t >= off) ? partial[t - off] : 0u;
        __syncthreads();
        partial[t] += v;
        __syncthreads();
    }
    unsigned run = partial[t] - sum;
    #pragma unroll
    for (int k = 0; k < 32; k++) {
        unsigned v = vals[k];
        g_hist[t * 32 + k] = run;
        run += v;
    }
}

__global__ void scatter_kernel(int n)
{
    int i = blockIdx.x * blockDim.x + threadIdx.x;
    if (i >= n) return;
    unsigned pos = atomicAdd(&g_hist[g_key[i]], 1u);
    g_order[pos] = i;
}

// --------------------------- bilinear sample (float4) -----------------------
__device__ __forceinline__ float4 bsample4(const float* __restrict__ T, int r,
                                           float u, float v, int c4)
{
    float fr = (float)(r - 1);
    float fx = (u + 1.0f) * 0.5f * fr;
    float fy = (v + 1.0f) * 0.5f * fr;
    float flx = floorf(fx);
    float fly = floorf(fy);
    flx = fminf(fmaxf(flx, 0.0f), (float)(r - 2));
    fly = fminf(fmaxf(fly, 0.0f), (float)(r - 2));
    float wx = fx - flx;
    float wy = fy - fly;
    int ix = (int)flx;
    int iy = (int)fly;
    const float4* b = (const float4*)(T + (((long)(iy * r + ix)) << 5)) + c4;
    long rowStep4 = ((long)r) << 3;        // next y row in float4 units
    float4 v00 = __ldg(b);
    float4 v01 = __ldg(b + 8);
    float4 v10 = __ldg(b + rowStep4);
    float4 v11 = __ldg(b + rowStep4 + 8);
    float4 o;
    float t0, t1;
    t0 = v00.x + (v01.x - v00.x) * wx; t1 = v10.x + (v11.x - v10.x) * wx;
    o.x = t0 + (t1 - t0) * wy;
    t0 = v00.y + (v01.y - v00.y) * wx; t1 = v10.y + (v11.y - v10.y) * wx;
    o.y = t0 + (t1 - t0) * wy;
    t0 = v00.z + (v01.z - v00.z) * wx; t1 = v10.z + (v11.z - v10.z) * wx;
    o.z = t0 + (t1 - t0) * wy;
    t0 = v00.w + (v01.w - v00.w) * wx; t1 = v10.w + (v11.w - v10.w) * wx;
    o.w = t0 + (t1 - t0) * wy;
    return o;
}

// --------------------------- main field kernel ------------------------------
// 4 points per warp. lane = p*8 + c4 ; lane handles channels [c4*4, c4*4+4).
__global__ void __launch_bounds__(256) field_kernel(
    const float* __restrict__ pts,
    const float* __restrict__ aabb,
    const float* __restrict__ lc0,
    const float* __restrict__ ks,
    const float* __restrict__ kpb,
    float* __restrict__ out,
    int npts, int useOrder)
{
    int gwarp = (int)((blockIdx.x * (long)blockDim.x + threadIdx.x) >> 5);
    int lane  = threadIdx.x & 31;
    int pslot = lane >> 3;               // point within warp: 0..3
    int c4    = lane & 7;                // channel quad: 0..7

    int slot = gwarp * 4 + pslot;
    if (slot >= npts) return;
    int pid = useOrder ? g_order[slot] : slot;

    const float* pp = pts + 3L * pid;
    float px = __ldg(&pp[0]);
    float py = __ldg(&pp[1]);
    float pz = __ldg(&pp[2]);

    float a0x = __ldg(&aabb[0]), a0y = __ldg(&aabb[1]), a0z = __ldg(&aabb[2]);
    float a1x = __ldg(&aabb[3]), a1y = __ldg(&aabb[4]), a1z = __ldg(&aabb[5]);

    float xs0 = (px - a0x) * (2.0f / (a1x - a0x)) - 1.0f;
    float xs1 = (py - a0y) * (2.0f / (a1y - a0y)) - 1.0f;
    float xs2 = (pz - a0z) * (2.0f / (a1z - a0z)) - 1.0f;

    long outBase = (long)pid * 128;
    const float4* kpb4 = (const float4*)kpb;

    const int resArr[3] = {128, 256, 512};
    #pragma unroll
    for (int s = 0; s < 3; s++) {
        int r = resArr[s];
        const float* T0 = g_planesT + c_plane_off[s * 3 + 0];
        const float* T1 = g_planesT + c_plane_off[s * 3 + 1];
        const float* T2 = g_planesT + c_plane_off[s * 3 + 2];
        float4 f0 = bsample4(T0, r, xs0, xs1, c4);
        float4 f1 = bsample4(T1, r, xs0, xs2, c4);
        float4 f2 = bsample4(T2, r, xs1, xs2, c4);
        float4 bias = __ldg(kpb4 + s * 8 + c4);
        float4 o;
        o.x = f0.x * f1.x * f2.x + bias.x;
        o.y = f0.y * f1.y * f2.y + bias.y;
        o.z = f0.z * f1.z * f2.z + bias.z;
        o.w = f0.w * f1.w * f2.w + bias.w;
        *(float4*)(out + outBase + s * 32 + (c4 << 2)) = o;
    }

    // ---- RBF features over 64^3 grid on [-1,1]
    const float interval = 2.0f / (float)(NSIDE - 1);
    float c0 = floorf((xs0 + 1.0f) / interval);
    float c1 = floorf((xs1 + 1.0f) / interval);
    float c2 = floorf((xs2 + 1.0f) / interval);
    c0 = fminf(fmaxf(c0, 0.0f), (float)(NSIDE - 2));
    c1 = fminf(fmaxf(c1, 0.0f), (float)(NSIDE - 2));
    c2 = fminf(fmaxf(c2, 0.0f), (float)(NSIDE - 2));
    int ci0 = (int)c0, ci1 = (int)c1, ci2 = (int)c2;

    float4 acc = make_float4(0.f, 0.f, 0.f, 0.f);
    float wsum = 0.0f;
    #pragma unroll
    for (int k = 0; k < 8; k++) {
        int i0 = ci0 + ((k >> 2) & 1);
        int i1 = ci1 + ((k >> 1) & 1);
        int i2 = ci2 + (k & 1);
        int idx = (i0 * NSIDE + i1) * NSIDE + i2;
        float k0 = -1.0f + (float)i0 * interval;
        float k1 = -1.0f + (float)i1 * interval;
        float k2 = -1.0f + (float)i2 * interval;
        float d0 = xs0 - k0;
        float d1 = xs1 - k1;
        float d2 = xs2 - k2;
        float dist2 = d0 * d0 + d1 * d1 + d2 * d2;
        float sv = __ldg(&ks[idx]);
        float phi = 1.0f / (1.0f + dist2 * sv * sv);
        wsum += phi;
        float4 code = __ldg((const float4*)(lc0 + ((long)idx << 5)) + c4);
        acc.x += phi * code.x;
        acc.y += phi * code.y;
        acc.z += phi * code.z;
        acc.w += phi * code.w;
    }
    float inv = 1.0f / (wsum + 1e-8f);
    float4 bias = __ldg(kpb4 + 24 + c4);
    float4 o;
    o.x = acc.x * inv + bias.x;
    o.y = acc.y * inv + bias.y;
    o.z = acc.z * inv + bias.z;
    o.w = acc.w * inv + bias.w;
    *(float4*)(out + outBase + 96 + (c4 << 2)) = o;
}

// ------------------------------ launcher ------------------------------------
extern "C" void kernel_launch(void* const* d_in, const int* in_sizes, int n_in,
                              void* d_out, int out_size)
{
    const float* pts  = (const float*)d_in[0];
    const float* aabb = (const float*)d_in[1];
    const float* lc0  = (const float*)d_in[11];
    const float* ks   = (const float*)d_in[12];
    const float* kpb  = (const float*)d_in[13];
    float* out = (float*)d_out;

    int npts = in_sizes[0] / 3;

    PlanePtrs ptrs;
    for (int i = 0; i < 9; i++) ptrs.p[i] = (const float*)d_in[2 + i];
    transpose_all_kernel<<<8064, 256>>>(ptrs);

    int useOrder = (npts <= MAXN) ? 1 : 0;
    if (useOrder) {
        zero_hist_kernel<<<NBUCK / 256, 256>>>();
        hist_kernel<<<(npts + 255) / 256, 256>>>(pts, aabb, npts);
        scan_kernel<<<1, 1024>>>();
        scatter_kernel<<<(npts + 255) / 256, 256>>>(npts);
    }

    // 4 points per warp, 8 warps per block -> 32 points per block
    int pointsPerBlock = 32;
    int blocks = (npts + pointsPerBlock - 1) / pointsPerBlock;
    field_kernel<<<blocks, 256>>>(pts, aabb, lc0, ks, kpb, out, npts, useOrder);
}

// round 4
// speedup vs baseline: 2.2282x; 1.2374x over previous
#include <cuda_runtime.h>
#include <cuda_fp16.h>

// ---------------------------------------------------------------------------
// KPlaneRBFField on GB300 — round 4.
//  Pass 1: fused transpose of 9 planes [32,r,r] -> fp16 [r,r,32] (66 MB,
//          L2-resident; 2 x-adjacent corners share one 128B line).
//  Pass 1b: lc0 -> fp16 copy (16.5 MB).
//  Pass 2: Morton counting sort (32^3), now with PARALLEL scan (32-block
//          shuffle scan + 1-warp top scan; offset folded into scatter).
//  Pass 3: field kernel, 4 points/warp, lane = point*8 + chan-quad,
//          fp16 loads -> fp32 interp, float4 stores.
// ---------------------------------------------------------------------------

#define NSIDE 64
#define MAXN  524288
#define NBUCK 32768
#define TP_POS 128

__device__ __half   g_planesTh[33030144];  // 66 MB transposed fp16 planes
__device__ __half   g_lc0h[8388608];       // 16.5 MB fp16 codes
__device__ unsigned g_hist[NBUCK];
__device__ unsigned g_blksum[32];
__device__ unsigned g_blkoff[32];
__device__ unsigned g_key[MAXN];
__device__ int      g_order[MAXN];

__constant__ long c_plane_off[9] = {
    0L,        524288L,   1048576L,
    1572864L,  3670016L,  5767168L,
    7864320L,  16252928L, 24641536L
};
__constant__ int c_blkCum[10] = {0,128,256,384,896,1408,1920,3968,6016,8064};
__constant__ int c_res[9]     = {128,128,128,256,256,256,512,512,512};

struct PlanePtrs { const float* p[9]; };

// --------------------------- fused transpose (fp32 -> fp16) -----------------
__global__ void __launch_bounds__(256) transpose_all_kernel(PlanePtrs ptrs)
{
    __shared__ float tile[TP_POS][33];
    int b = blockIdx.x;
    int pi = 0;
    #pragma unroll
    for (int i = 1; i < 9; i++) pi += (b >= c_blkCum[i]) ? 1 : 0;
    int r  = c_res[pi];
    int rr = r * r;
    int posBase = (b - c_blkCum[pi]) * TP_POS;
    const float* src = ptrs.p[pi];

    int tid = threadIdx.x;
    const float4* src4 = (const float4*)src;
    int rr4 = rr >> 2;
    int pb4 = posBase >> 2;

    #pragma unroll
    for (int it = 0; it < 4; it++) {
        int v  = tid + it * 256;        // 0..1023
        int ch = v >> 5;
        int pv = v & 31;
        float4 val = src4[(long)ch * rr4 + pb4 + pv];
        int p = pv << 2;
        tile[p + 0][ch] = val.x;
        tile[p + 1][ch] = val.y;
        tile[p + 2][ch] = val.z;
        tile[p + 3][ch] = val.w;
    }
    __syncthreads();

    uint2* dst2 = (uint2*)(g_planesTh + c_plane_off[pi] + (long)posBase * 32);
    #pragma unroll
    for (int it = 0; it < 4; it++) {
        int v  = tid + it * 256;        // = p*8 + c4idx
        int p  = v >> 3;
        int c4 = (v & 7) << 2;
        __half2 h0 = __floats2half2_rn(tile[p][c4 + 0], tile[p][c4 + 1]);
        __half2 h1 = __floats2half2_rn(tile[p][c4 + 2], tile[p][c4 + 3]);
        uint2 o = make_uint2(*(unsigned*)&h0, *(unsigned*)&h1);
        dst2[v] = o;
    }
}

// --------------------------- lc0 fp16 conversion ----------------------------
__global__ void __launch_bounds__(256) lc0_convert_kernel(const float* __restrict__ lc0)
{
    int i = blockIdx.x * blockDim.x + threadIdx.x;   // one float4 per thread
    float4 v = __ldg((const float4*)lc0 + i);
    __half2 h0 = __floats2half2_rn(v.x, v.y);
    __half2 h1 = __floats2half2_rn(v.z, v.w);
    ((uint2*)g_lc0h)[i] = make_uint2(*(unsigned*)&h0, *(unsigned*)&h1);
}

// --------------------------- sorting kernels --------------------------------
__device__ __forceinline__ unsigned spread3(unsigned x)
{
    x &= 0x3FF;
    x = (x | (x << 16)) & 0x30000FF;
    x = (x | (x << 8))  & 0x300F00F;
    x = (x | (x << 4))  & 0x30C30C3;
    x = (x | (x << 2))  & 0x9249249;
    return x;
}

__global__ void zero_hist_kernel()
{
    g_hist[blockIdx.x * 256 + threadIdx.x] = 0;
}

__global__ void hist_kernel(const float* __restrict__ pts,
                            const float* __restrict__ aabb, int n)
{
    int i = blockIdx.x * blockDim.x + threadIdx.x;
    if (i >= n) return;
    float a0x = aabb[0], a0y = aabb[1], a0z = aabb[2];
    float a1x = aabb[3], a1y = aabb[4], a1z = aabb[5];
    float x = (pts[3 * i + 0] - a0x) * (2.0f / (a1x - a0x)) - 1.0f;
    float y = (pts[3 * i + 1] - a0y) * (2.0f / (a1y - a0y)) - 1.0f;
    float z = (pts[3 * i + 2] - a0z) * (2.0f / (a1z - a0z)) - 1.0f;
    int qx = min(max((int)((x + 1.0f) * 16.0f), 0), 31);
    int qy = min(max((int)((y + 1.0f) * 16.0f), 0), 31);
    int qz = min(max((int)((z + 1.0f) * 16.0f), 0), 31);
    unsigned key = (spread3(qx) << 2) | (spread3(qy) << 1) | spread3(qz);
    g_key[i] = key;
    atomicAdd(&g_hist[key], 1u);
}

// scan1: 32 blocks x 1024 threads, 1 bucket/thread. Block-local exclusive scan
// written back to g_hist; block total to g_blksum.
__global__ void __launch_bounds__(1024) scan1_kernel()
{
    __shared__ unsigned wsum[32];
    int t = threadIdx.x;
    int lane = t & 31;
    int wid = t >> 5;
    int i = blockIdx.x * 1024 + t;
    unsigned v = g_hist[i];

    unsigned x = v;
    #pragma unroll
    for (int off = 1; off < 32; off <<= 1) {
        unsigned y = __shfl_up_sync(0xFFFFFFFFu, x, off);
        if (lane >= off) x += y;
    }
    if (lane == 31) wsum[wid] = x;
    __syncthreads();
    if (wid == 0) {
        unsigned w = wsum[lane];
        unsigned ww = w;
        #pragma unroll
        for (int off = 1; off < 32; off <<= 1) {
            unsigned y = __shfl_up_sync(0xFFFFFFFFu, ww, off);
            if (lane >= off) ww += y;
        }
        wsum[lane] = ww - w;           // exclusive warp offset
        if (lane == 31) g_blksum[blockIdx.x] = ww;   // block total
    }
    __syncthreads();
    unsigned incl = x + wsum[wid];
    g_hist[i] = incl - v;              // block-local exclusive prefix
}

// scan2: one warp scans the 32 block totals -> exclusive block offsets.
__global__ void scan2_kernel()
{
    int lane = threadIdx.x;
    unsigned v = g_blksum[lane];
    unsigned x = v;
    #pragma unroll
    for (int off = 1; off < 32; off <<= 1) {
        unsigned y = __shfl_up_sync(0xFFFFFFFFu, x, off);
        if (lane >= off) x += y;
    }
    g_blkoff[lane] = x - v;
}

__global__ void scatter_kernel(int n)
{
    int i = blockIdx.x * blockDim.x + threadIdx.x;
    if (i >= n) return;
    unsigned key = g_key[i];
    unsigned pos = atomicAdd(&g_hist[key], 1u) + g_blkoff[key >> 10];
    g_order[pos] = i;
}

// --------------------------- fp16 helpers -----------------------------------
__device__ __forceinline__ float4 h4tof4(uint2 u)
{
    float2 lo = __half22float2(*(const __half2*)&u.x);
    float2 hi = __half22float2(*(const __half2*)&u.y);
    return make_float4(lo.x, lo.y, hi.x, hi.y);
}

// --------------------------- bilinear sample (fp16 x4) ----------------------
__device__ __forceinline__ float4 bsample4h(const __half* __restrict__ T, int r,
                                            float u, float v, int c4)
{
    float fr = (float)(r - 1);
    float fx = (u + 1.0f) * 0.5f * fr;
    float fy = (v + 1.0f) * 0.5f * fr;
    float flx = fminf(fmaxf(floorf(fx), 0.0f), (float)(r - 2));
    float fly = fminf(fmaxf(floorf(fy), 0.0f), (float)(r - 2));
    float wx = fx - flx;
    float wy = fy - fly;
    int ix = (int)flx;
    int iy = (int)fly;
    const __half* b = T + (((long)(iy * r + ix)) << 5) + (c4 << 2);
    long rs = ((long)r) << 5;
    float4 v00 = h4tof4(__ldg((const uint2*)b));
    float4 v01 = h4tof4(__ldg((const uint2*)(b + 32)));
    float4 v10 = h4tof4(__ldg((const uint2*)(b + rs)));
    float4 v11 = h4tof4(__ldg((const uint2*)(b + rs + 32)));
    float4 o;
    float t0, t1;
    t0 = v00.x + (v01.x - v00.x) * wx; t1 = v10.x + (v11.x - v10.x) * wx;
    o.x = t0 + (t1 - t0) * wy;
    t0 = v00.y + (v01.y - v00.y) * wx; t1 = v10.y + (v11.y - v10.y) * wx;
    o.y = t0 + (t1 - t0) * wy;
    t0 = v00.z + (v01.z - v00.z) * wx; t1 = v10.z + (v11.z - v10.z) * wx;
    o.z = t0 + (t1 - t0) * wy;
    t0 = v00.w + (v01.w - v00.w) * wx; t1 = v10.w + (v11.w - v10.w) * wx;
    o.w = t0 + (t1 - t0) * wy;
    return o;
}

// --------------------------- main field kernel ------------------------------
__global__ void __launch_bounds__(256) field_kernel(
    const float* __restrict__ pts,
    const float* __restrict__ aabb,
    const float* __restrict__ ks,
    const float* __restrict__ kpb,
    float* __restrict__ out,
    int npts, int useOrder)
{
    int gwarp = (int)((blockIdx.x * (long)blockDim.x + threadIdx.x) >> 5);
    int lane  = threadIdx.x & 31;
    int pslot = lane >> 3;
    int c4    = lane & 7;

    int slot = gwarp * 4 + pslot;
    if (slot >= npts) return;
    int pid = useOrder ? g_order[slot] : slot;

    const float* pp = pts + 3L * pid;
    float px = __ldg(&pp[0]);
    float py = __ldg(&pp[1]);
    float pz = __ldg(&pp[2]);

    float a0x = __ldg(&aabb[0]), a0y = __ldg(&aabb[1]), a0z = __ldg(&aabb[2]);
    float a1x = __ldg(&aabb[3]), a1y = __ldg(&aabb[4]), a1z = __ldg(&aabb[5]);

    float xs0 = (px - a0x) * (2.0f / (a1x - a0x)) - 1.0f;
    float xs1 = (py - a0y) * (2.0f / (a1y - a0y)) - 1.0f;
    float xs2 = (pz - a0z) * (2.0f / (a1z - a0z)) - 1.0f;

    long outBase = (long)pid * 128;
    const float4* kpb4 = (const float4*)kpb;

    const int resArr[3] = {128, 256, 512};
    #pragma unroll
    for (int s = 0; s < 3; s++) {
        int r = resArr[s];
        const __half* T0 = g_planesTh + c_plane_off[s * 3 + 0];
        const __half* T1 = g_planesTh + c_plane_off[s * 3 + 1];
        const __half* T2 = g_planesTh + c_plane_off[s * 3 + 2];
        float4 f0 = bsample4h(T0, r, xs0, xs1, c4);
        float4 f1 = bsample4h(T1, r, xs0, xs2, c4);
        float4 f2 = bsample4h(T2, r, xs1, xs2, c4);
        float4 bias = __ldg(kpb4 + s * 8 + c4);
        float4 o;
        o.x = f0.x * f1.x * f2.x + bias.x;
        o.y = f0.y * f1.y * f2.y + bias.y;
        o.z = f0.z * f1.z * f2.z + bias.z;
        o.w = f0.w * f1.w * f2.w + bias.w;
        *(float4*)(out + outBase + s * 32 + (c4 << 2)) = o;
    }

    // ---- RBF features over 64^3 grid on [-1,1]
    const float interval = 2.0f / (float)(NSIDE - 1);
    float c0 = floorf((xs0 + 1.0f) / interval);
    float c1 = floorf((xs1 + 1.0f) / interval);
    float c2 = floorf((xs2 + 1.0f) / interval);
    c0 = fminf(fmaxf(c0, 0.0f), (float)(NSIDE - 2));
    c1 = fminf(fmaxf(c1, 0.0f), (float)(NSIDE - 2));
    c2 = fminf(fmaxf(c2, 0.0f), (float)(NSIDE - 2));
    int ci0 = (int)c0, ci1 = (int)c1, ci2 = (int)c2;

    float4 acc = make_float4(0.f, 0.f, 0.f, 0.f);
    float wsum = 0.0f;
    #pragma unroll
    for (int k = 0; k < 8; k++) {
        int i0 = ci0 + ((k >> 2) & 1);
        int i1 = ci1 + ((k >> 1) & 1);
        int i2 = ci2 + (k & 1);
        int idx = (i0 * NSIDE + i1) * NSIDE + i2;
        float k0 = -1.0f + (float)i0 * interval;
        float k1 = -1.0f + (float)i1 * interval;
        float k2 = -1.0f + (float)i2 * interval;
        float d0 = xs0 - k0;
        float d1 = xs1 - k1;
        float d2 = xs2 - k2;
        float dist2 = d0 * d0 + d1 * d1 + d2 * d2;
        float sv = __ldg(&ks[idx]);
        float phi = 1.0f / (1.0f + dist2 * sv * sv);
        wsum += phi;
        float4 code = h4tof4(__ldg((const uint2*)(g_lc0h + ((long)idx << 5)) + c4));
        acc.x += phi * code.x;
        acc.y += phi * code.y;
        acc.z += phi * code.z;
        acc.w += phi * code.w;
    }
    float inv = 1.0f / (wsum + 1e-8f);
    float4 bias = __ldg(kpb4 + 24 + c4);
    float4 o;
    o.x = acc.x * inv + bias.x;
    o.y = acc.y * inv + bias.y;
    o.z = acc.z * inv + bias.z;
    o.w = acc.w * inv + bias.w;
    *(float4*)(out + outBase + 96 + (c4 << 2)) = o;
}

// ------------------------------ launcher ------------------------------------
extern "C" void kernel_launch(void* const* d_in, const int* in_sizes, int n_in,
                              void* d_out, int out_size)
{
    const float* pts  = (const float*)d_in[0];
    const float* aabb = (const float*)d_in[1];
    const float* lc0  = (const float*)d_in[11];
    const float* ks   = (const float*)d_in[12];
    const float* kpb  = (const float*)d_in[13];
    float* out = (float*)d_out;

    int npts = in_sizes[0] / 3;

    PlanePtrs ptrs;
    for (int i = 0; i < 9; i++) ptrs.p[i] = (const float*)d_in[2 + i];
    transpose_all_kernel<<<8064, 256>>>(ptrs);

    // lc0 -> fp16 : 8,388,608 floats = 2,097,152 float4
    lc0_convert_kernel<<<8192, 256>>>(lc0);

    int useOrder = (npts <= MAXN) ? 1 : 0;
    if (useOrder) {
        zero_hist_kernel<<<NBUCK / 256, 256>>>();
        hist_kernel<<<(npts + 255) / 256, 256>>>(pts, aabb, npts);
        scan1_kernel<<<32, 1024>>>();
        scan2_kernel<<<1, 32>>>();
        scatter_kernel<<<(npts + 255) / 256, 256>>>(npts);
    }

    int pointsPerBlock = 32;     // 4 points/warp * 8 warps
    int blocks = (npts + pointsPerBlock - 1) / pointsPerBlock;
    field_kernel<<<blocks, 256>>>(pts, aabb, ks, kpb, out, npts, useOrder);
}

// round 5
// speedup vs baseline: 2.2650x; 1.0165x over previous
#include <cuda_runtime.h>
#include <cuda_fp16.h>

// ---------------------------------------------------------------------------
// KPlaneRBFField on GB300 — round 5.
//  k1: fused transpose 9 planes [32,r,r] -> fp16 [r,r,32]  +  lc0 -> fp16
//      + zero hist (grid 16384).
//  k2: Morton histogram (32^3).
//  k3: parallel scan (32 blocks).
//  k4: scatter: computes final position, writes SORTED normalized coords
//      (xs0,xs1,xs2, pid) as float4  (scan2 folded in).
//  k5: field: 8 points/warp, lane = point*4 + chan-oct; every plane corner is
//      ONE warp LDG.128 (64B fp16 row x 8 points); lc0 row likewise.
// ---------------------------------------------------------------------------

#define NSIDE 64
#define MAXN  524288
#define NBUCK 32768
#define TP_POS 128

__device__ __half   g_planesTh[33030144];  // 66 MB transposed fp16 planes
__device__ __half   g_lc0h[8388608];       // 16.5 MB fp16 codes
__device__ unsigned g_hist[NBUCK];
__device__ unsigned g_blksum[32];
__device__ unsigned g_key[MAXN];
__device__ float4   g_spts[MAXN];          // sorted (xs0,xs1,xs2,pid)

__constant__ long c_plane_off[9] = {
    0L,        524288L,   1048576L,
    1572864L,  3670016L,  5767168L,
    7864320L,  16252928L, 24641536L
};
__constant__ int c_blkCum[10] = {0,128,256,384,896,1408,1920,3968,6016,8064};
__constant__ int c_res[9]     = {128,128,128,256,256,256,512,512,512};

struct PlanePtrs { const float* p[9]; const float* lc0; };

// ---------------- k1: transpose + lc0 convert + zero hist -------------------
__global__ void __launch_bounds__(256) prep_kernel(PlanePtrs ptrs)
{
    int b = blockIdx.x;
    int tid = threadIdx.x;

    if (b >= 16256) {                       // zero hist: 128 blocks
        g_hist[(b - 16256) * 256 + tid] = 0;
        return;
    }
    if (b >= 8064) {                        // lc0 convert: 8192 blocks
        int i = (b - 8064) * 256 + tid;     // one float4 per thread
        float4 v = __ldg((const float4*)ptrs.lc0 + i);
        __half2 h0 = __floats2half2_rn(v.x, v.y);
        __half2 h1 = __floats2half2_rn(v.z, v.w);
        ((uint2*)g_lc0h)[i] = make_uint2(*(unsigned*)&h0, *(unsigned*)&h1);
        return;
    }

    // plane transpose
    __shared__ float tile[TP_POS][33];
    int pi = 0;
    #pragma unroll
    for (int i = 1; i < 9; i++) pi += (b >= c_blkCum[i]) ? 1 : 0;
    int r  = c_res[pi];
    int rr = r * r;
    int posBase = (b - c_blkCum[pi]) * TP_POS;
    const float4* src4 = (const float4*)ptrs.p[pi];
    int rr4 = rr >> 2;
    int pb4 = posBase >> 2;

    #pragma unroll
    for (int it = 0; it < 4; it++) {
        int v  = tid + it * 256;
        int ch = v >> 5;
        int pv = v & 31;
        float4 val = src4[(long)ch * rr4 + pb4 + pv];
        int p = pv << 2;
        tile[p + 0][ch] = val.x;
        tile[p + 1][ch] = val.y;
        tile[p + 2][ch] = val.z;
        tile[p + 3][ch] = val.w;
    }
    __syncthreads();

    uint2* dst2 = (uint2*)(g_planesTh + c_plane_off[pi] + (long)posBase * 32);
    #pragma unroll
    for (int it = 0; it < 4; it++) {
        int v  = tid + it * 256;
        int p  = v >> 3;
        int c4 = (v & 7) << 2;
        __half2 h0 = __floats2half2_rn(tile[p][c4 + 0], tile[p][c4 + 1]);
        __half2 h1 = __floats2half2_rn(tile[p][c4 + 2], tile[p][c4 + 3]);
        dst2[v] = make_uint2(*(unsigned*)&h0, *(unsigned*)&h1);
    }
}

// ---------------- sorting --------------------------------------------------
__device__ __forceinline__ unsigned spread3(unsigned x)
{
    x &= 0x3FF;
    x = (x | (x << 16)) & 0x30000FF;
    x = (x | (x << 8))  & 0x300F00F;
    x = (x | (x << 4))  & 0x30C30C3;
    x = (x | (x << 2))  & 0x9249249;
    return x;
}

__global__ void hist_kernel(const float* __restrict__ pts,
                            const float* __restrict__ aabb, int n)
{
    int i = blockIdx.x * blockDim.x + threadIdx.x;
    if (i >= n) return;
    float a0x = aabb[0], a0y = aabb[1], a0z = aabb[2];
    float a1x = aabb[3], a1y = aabb[4], a1z = aabb[5];
    float x = (pts[3 * i + 0] - a0x) * (2.0f / (a1x - a0x)) - 1.0f;
    float y = (pts[3 * i + 1] - a0y) * (2.0f / (a1y - a0y)) - 1.0f;
    float z = (pts[3 * i + 2] - a0z) * (2.0f / (a1z - a0z)) - 1.0f;
    int qx = min(max((int)((x + 1.0f) * 16.0f), 0), 31);
    int qy = min(max((int)((y + 1.0f) * 16.0f), 0), 31);
    int qz = min(max((int)((z + 1.0f) * 16.0f), 0), 31);
    unsigned key = (spread3(qx) << 2) | (spread3(qy) << 1) | spread3(qz);
    g_key[i] = key;
    atomicAdd(&g_hist[key], 1u);
}

__global__ void __launch_bounds__(1024) scan1_kernel()
{
    __shared__ unsigned wsum[32];
    int t = threadIdx.x;
    int lane = t & 31;
    int wid = t >> 5;
    int i = blockIdx.x * 1024 + t;
    unsigned v = g_hist[i];

    unsigned x = v;
    #pragma unroll
    for (int off = 1; off < 32; off <<= 1) {
        unsigned y = __shfl_up_sync(0xFFFFFFFFu, x, off);
        if (lane >= off) x += y;
    }
    if (lane == 31) wsum[wid] = x;
    __syncthreads();
    if (wid == 0) {
        unsigned w = wsum[lane];
        unsigned ww = w;
        #pragma unroll
        for (int off = 1; off < 32; off <<= 1) {
            unsigned y = __shfl_up_sync(0xFFFFFFFFu, ww, off);
            if (lane >= off) ww += y;
        }
        wsum[lane] = ww - w;
        if (lane == 31) g_blksum[blockIdx.x] = ww;
    }
    __syncthreads();
    g_hist[i] = x + wsum[wid] - v;   // block-local exclusive prefix
}

// scatter: block offsets scanned in-block (scan2 folded in); writes sorted
// normalized coords + original pid.
__global__ void scatter_kernel(const float* __restrict__ pts,
                               const float* __restrict__ aabb, int n)
{
    __shared__ unsigned blkoff[32];
    int t = threadIdx.x;
    if (t < 32) {
        unsigned v = g_blksum[t];
        unsigned x = v;
        #pragma unroll
        for (int off = 1; off < 32; off <<= 1) {
            unsigned y = __shfl_up_sync(0xFFFFFFFFu, x, off);
            if (t >= off) x += y;
        }
        blkoff[t] = x - v;
    }
    __syncthreads();

    int i = blockIdx.x * blockDim.x + t;
    if (i >= n) return;
    unsigned key = g_key[i];
    unsigned pos = atomicAdd(&g_hist[key], 1u) + blkoff[key >> 10];

    float a0x = aabb[0], a0y = aabb[1], a0z = aabb[2];
    float a1x = aabb[3], a1y = aabb[4], a1z = aabb[5];
    float xs0 = (pts[3 * i + 0] - a0x) * (2.0f / (a1x - a0x)) - 1.0f;
    float xs1 = (pts[3 * i + 1] - a0y) * (2.0f / (a1y - a0y)) - 1.0f;
    float xs2 = (pts[3 * i + 2] - a0z) * (2.0f / (a1z - a0z)) - 1.0f;
    g_spts[pos] = make_float4(xs0, xs1, xs2, __int_as_float(i));
}

// fallback (npts > MAXN never expected; identity order)
__global__ void ident_kernel(const float* __restrict__ pts,
                             const float* __restrict__ aabb, int n)
{
    int i = blockIdx.x * blockDim.x + threadIdx.x;
    if (i >= n) return;
    float a0x = aabb[0], a0y = aabb[1], a0z = aabb[2];
    float a1x = aabb[3], a1y = aabb[4], a1z = aabb[5];
    float xs0 = (pts[3 * i + 0] - a0x) * (2.0f / (a1x - a0x)) - 1.0f;
    float xs1 = (pts[3 * i + 1] - a0y) * (2.0f / (a1y - a0y)) - 1.0f;
    float xs2 = (pts[3 * i + 2] - a0z) * (2.0f / (a1z - a0z)) - 1.0f;
    g_spts[i] = make_float4(xs0, xs1, xs2, __int_as_float(i));
}

// ---------------- fp16 helpers ----------------------------------------------
__device__ __forceinline__ void h8tof8(uint4 u, float* f)
{
    float2 p;
    p = __half22float2(*(const __half2*)&u.x); f[0] = p.x; f[1] = p.y;
    p = __half22float2(*(const __half2*)&u.y); f[2] = p.x; f[3] = p.y;
    p = __half22float2(*(const __half2*)&u.z); f[4] = p.x; f[5] = p.y;
    p = __half22float2(*(const __half2*)&u.w); f[6] = p.x; f[7] = p.y;
}

// bilinear sample of 8 channels (one uint4 per corner per lane)
__device__ __forceinline__ void bsample8h(const __half* __restrict__ T, int r,
                                          float u, float v, int c8, float* o)
{
    float fr = (float)(r - 1);
    float fx = (u + 1.0f) * 0.5f * fr;
    float fy = (v + 1.0f) * 0.5f * fr;
    float flx = fminf(fmaxf(floorf(fx), 0.0f), (float)(r - 2));
    float fly = fminf(fmaxf(floorf(fy), 0.0f), (float)(r - 2));
    float wx = fx - flx;
    float wy = fy - fly;
    int ix = (int)flx;
    int iy = (int)fly;
    const uint4* b = (const uint4*)(T + (((long)(iy * r + ix)) << 5)) + c8;
    long rs = ((long)r) << 2;              // row stride in uint4 units
    uint4 a00 = __ldg(b);
    uint4 a01 = __ldg(b + 4);
    uint4 a10 = __ldg(b + rs);
    uint4 a11 = __ldg(b + rs + 4);
    float f00[8], f01[8], f10[8], f11[8];
    h8tof8(a00, f00); h8tof8(a01, f01); h8tof8(a10, f10); h8tof8(a11, f11);
    #pragma unroll
    for (int k = 0; k < 8; k++) {
        float t0 = f00[k] + (f01[k] - f00[k]) * wx;
        float t1 = f10[k] + (f11[k] - f10[k]) * wx;
        o[k] = t0 + (t1 - t0) * wy;
    }
}

// ---------------- field kernel: 8 points/warp --------------------------------
__global__ void __launch_bounds__(256) field_kernel(
    const float* __restrict__ ks,
    const float* __restrict__ kpb,
    float* __restrict__ out,
    int npts)
{
    int gwarp = (int)((blockIdx.x * (long)blockDim.x + threadIdx.x) >> 5);
    int lane  = threadIdx.x & 31;
    int pslot = lane >> 2;               // point within warp: 0..7
    int c8    = lane & 3;                // channel oct: 0..3

    int slot = gwarp * 8 + pslot;
    if (slot >= npts) return;

    float4 sp = __ldg(&g_spts[slot]);    // coalesced: 8 pts x 16B = 128B/warp
    float xs0 = sp.x, xs1 = sp.y, xs2 = sp.z;
    int pid = __float_as_int(sp.w);

    long outBase = (long)pid * 128;
    const float4* kpb4 = (const float4*)kpb;

    const int resArr[3] = {128, 256, 512};
    #pragma unroll
    for (int s = 0; s < 3; s++) {
        int r = resArr[s];
        float f0[8], f1[8], f2[8];
        bsample8h(g_planesTh + c_plane_off[s * 3 + 0], r, xs0, xs1, c8, f0);
        bsample8h(g_planesTh + c_plane_off[s * 3 + 1], r, xs0, xs2, c8, f1);
        bsample8h(g_planesTh + c_plane_off[s * 3 + 2], r, xs1, xs2, c8, f2);
        float4 b0 = __ldg(kpb4 + s * 8 + c8 * 2);
        float4 b1 = __ldg(kpb4 + s * 8 + c8 * 2 + 1);
        float4 o0, o1;
        o0.x = f0[0] * f1[0] * f2[0] + b0.x;
        o0.y = f0[1] * f1[1] * f2[1] + b0.y;
        o0.z = f0[2] * f1[2] * f2[2] + b0.z;
        o0.w = f0[3] * f1[3] * f2[3] + b0.w;
        o1.x = f0[4] * f1[4] * f2[4] + b1.x;
        o1.y = f0[5] * f1[5] * f2[5] + b1.y;
        o1.z = f0[6] * f1[6] * f2[6] + b1.z;
        o1.w = f0[7] * f1[7] * f2[7] + b1.w;
        float* op = out + outBase + s * 32 + (c8 << 3);
        *(float4*)op = o0;
        *(float4*)(op + 4) = o1;
    }

    // ---- RBF features over 64^3 grid on [-1,1]
    const float interval = 2.0f / (float)(NSIDE - 1);
    float c0 = fminf(fmaxf(floorf((xs0 + 1.0f) / interval), 0.0f), (float)(NSIDE - 2));
    float c1 = fminf(fmaxf(floorf((xs1 + 1.0f) / interval), 0.0f), (float)(NSIDE - 2));
    float c2 = fminf(fmaxf(floorf((xs2 + 1.0f) / interval), 0.0f), (float)(NSIDE - 2));
    int ci0 = (int)c0, ci1 = (int)c1, ci2 = (int)c2;

    float acc[8] = {0.f, 0.f, 0.f, 0.f, 0.f, 0.f, 0.f, 0.f};
    float wsum = 0.0f;
    #pragma unroll
    for (int k = 0; k < 8; k++) {
        int i0 = ci0 + ((k >> 2) & 1);
        int i1 = ci1 + ((k >> 1) & 1);
        int i2 = ci2 + (k & 1);
        int idx = (i0 * NSIDE + i1) * NSIDE + i2;
        float k0 = -1.0f + (float)i0 * interval;
        float k1 = -1.0f + (float)i1 * interval;
        float k2 = -1.0f + (float)i2 * interval;
        float d0 = xs0 - k0;
        float d1 = xs1 - k1;
        float d2 = xs2 - k2;
        float dist2 = d0 * d0 + d1 * d1 + d2 * d2;
        float sv = __ldg(&ks[idx]);
        float phi = 1.0f / (1.0f + dist2 * sv * sv);
        wsum += phi;
        uint4 cu = __ldg((const uint4*)(g_lc0h + ((long)idx << 5)) + c8);
        float code[8];
        h8tof8(cu, code);
        #pragma unroll
        for (int j = 0; j < 8; j++) acc[j] += phi * code[j];
    }
    float inv = 1.0f / (wsum + 1e-8f);
    float4 b0 = __ldg(kpb4 + 24 + c8 * 2);
    float4 b1 = __ldg(kpb4 + 24 + c8 * 2 + 1);
    float4 o0, o1;
    o0.x = acc[0] * inv + b0.x;
    o0.y = acc[1] * inv + b0.y;
    o0.z = acc[2] * inv + b0.z;
    o0.w = acc[3] * inv + b0.w;
    o1.x = acc[4] * inv + b1.x;
    o1.y = acc[5] * inv + b1.y;
    o1.z = acc[6] * inv + b1.z;
    o1.w = acc[7] * inv + b1.w;
    float* op = out + outBase + 96 + (c8 << 3);
    *(float4*)op = o0;
    *(float4*)(op + 4) = o1;
}

// ------------------------------ launcher ------------------------------------
extern "C" void kernel_launch(void* const* d_in, const int* in_sizes, int n_in,
                              void* d_out, int out_size)
{
    const float* pts  = (const float*)d_in[0];
    const float* aabb = (const float*)d_in[1];
    const float* lc0  = (const float*)d_in[11];
    const float* ks   = (const float*)d_in[12];
    const float* kpb  = (const float*)d_in[13];
    float* out = (float*)d_out;

    int npts = in_sizes[0] / 3;

    PlanePtrs ptrs;
    for (int i = 0; i < 9; i++) ptrs.p[i] = (const float*)d_in[2 + i];
    ptrs.lc0 = lc0;
    prep_kernel<<<16384, 256>>>(ptrs);   // transpose + lc0->fp16 + zero hist

    if (npts <= MAXN) {
        hist_kernel<<<(npts + 255) / 256, 256>>>(pts, aabb, npts);
        scan1_kernel<<<32, 1024>>>();
        scatter_kernel<<<(npts + 255) / 256, 256>>>(pts, aabb, npts);
    } else {
        ident_kernel<<<(npts + 255) / 256, 256>>>(pts, aabb, npts);
    }

    // 8 points/warp, 8 warps/block -> 64 points per block
    int blocks = (npts + 63) / 64;
    field_kernel<<<blocks, 256>>>(ks, kpb, out, npts);
}

// round 6
// speedup vs baseline: 2.3579x; 1.0410x over previous
#include <cuda_runtime.h>
#include <cuda_fp16.h>

// ---------------------------------------------------------------------------
// KPlaneRBFField on GB300 — round 6.
//  memset:  g_hist = 0 (graph memset node).
//  k1 prep: transpose 9 planes [32,r,r] -> fp16 [r,r,32] + lc0 -> fp16
//           + Morton histogram (hist folded in; field is now launch #4).
//  k2 scan1: parallel scan (32 blocks).
//  k3 scatter: writes SORTED (xs0,xs1,xs2,pid) float4.
//  k4 field: 8 pts/warp; batched 12-load plane sampling per scale (MLP),
//           batched RBF loads, __stcs streaming output stores (protect L2).
// ---------------------------------------------------------------------------

#define NSIDE 64
#define MAXN  524288
#define NBUCK 32768
#define TP_POS 128

__device__ __half   g_planesTh[33030144];  // 66 MB transposed fp16 planes
__device__ __half   g_lc0h[8388608];       // 16.5 MB fp16 codes
__device__ unsigned g_hist[NBUCK];
__device__ unsigned g_blksum[32];
__device__ unsigned g_key[MAXN];
__device__ float4   g_spts[MAXN];          // sorted (xs0,xs1,xs2,pid)

__constant__ int c_plane_off[9] = {
    0,        524288,   1048576,
    1572864,  3670016,  5767168,
    7864320,  16252928, 24641536
};
__constant__ int c_blkCum[10] = {0,128,256,384,896,1408,1920,3968,6016,8064};
__constant__ int c_res[9]     = {128,128,128,256,256,256,512,512,512};

struct PrepArgs {
    const float* p[9];
    const float* lc0;
    const float* pts;
    const float* aabb;
    int n;
};

__device__ __forceinline__ unsigned spread3(unsigned x)
{
    x &= 0x3FF;
    x = (x | (x << 16)) & 0x30000FF;
    x = (x | (x << 8))  & 0x300F00F;
    x = (x | (x << 4))  & 0x30C30C3;
    x = (x | (x << 2))  & 0x9249249;
    return x;
}

// ---------------- k1: transpose + lc0 convert + histogram -------------------
__global__ void __launch_bounds__(256) prep_kernel(PrepArgs a)
{
    int b = blockIdx.x;
    int tid = threadIdx.x;

    if (b >= 16256) {                       // Morton histogram
        int i = (b - 16256) * 256 + tid;
        if (i >= a.n) return;
        float a0x = a.aabb[0], a0y = a.aabb[1], a0z = a.aabb[2];
        float a1x = a.aabb[3], a1y = a.aabb[4], a1z = a.aabb[5];
        float x = (a.pts[3 * i + 0] - a0x) * (2.0f / (a1x - a0x)) - 1.0f;
        float y = (a.pts[3 * i + 1] - a0y) * (2.0f / (a1y - a0y)) - 1.0f;
        float z = (a.pts[3 * i + 2] - a0z) * (2.0f / (a1z - a0z)) - 1.0f;
        int qx = min(max((int)((x + 1.0f) * 16.0f), 0), 31);
        int qy = min(max((int)((y + 1.0f) * 16.0f), 0), 31);
        int qz = min(max((int)((z + 1.0f) * 16.0f), 0), 31);
        unsigned key = (spread3(qx) << 2) | (spread3(qy) << 1) | spread3(qz);
        g_key[i] = key;
        atomicAdd(&g_hist[key], 1u);
        return;
    }
    if (b >= 8064) {                        // lc0 convert
        int i = (b - 8064) * 256 + tid;
        float4 v = __ldg((const float4*)a.lc0 + i);
        __half2 h0 = __floats2half2_rn(v.x, v.y);
        __half2 h1 = __floats2half2_rn(v.z, v.w);
        ((uint2*)g_lc0h)[i] = make_uint2(*(unsigned*)&h0, *(unsigned*)&h1);
        return;
    }

    // plane transpose
    __shared__ float tile[TP_POS][33];
    int pi = 0;
    #pragma unroll
    for (int i = 1; i < 9; i++) pi += (b >= c_blkCum[i]) ? 1 : 0;
    int r  = c_res[pi];
    int rr = r * r;
    int posBase = (b - c_blkCum[pi]) * TP_POS;
    const float4* src4 = (const float4*)a.p[pi];
    int rr4 = rr >> 2;
    int pb4 = posBase >> 2;

    #pragma unroll
    for (int it = 0; it < 4; it++) {
        int v  = tid + it * 256;
        int ch = v >> 5;
        int pv = v & 31;
        float4 val = src4[ch * rr4 + pb4 + pv];
        int p = pv << 2;
        tile[p + 0][ch] = val.x;
        tile[p + 1][ch] = val.y;
        tile[p + 2][ch] = val.z;
        tile[p + 3][ch] = val.w;
    }
    __syncthreads();

    uint2* dst2 = (uint2*)(g_planesTh + c_plane_off[pi]) + posBase * 8;
    #pragma unroll
    for (int it = 0; it < 4; it++) {
        int v  = tid + it * 256;
        int p  = v >> 3;
        int c4 = (v & 7) << 2;
        __half2 h0 = __floats2half2_rn(tile[p][c4 + 0], tile[p][c4 + 1]);
        __half2 h1 = __floats2half2_rn(tile[p][c4 + 2], tile[p][c4 + 3]);
        dst2[v] = make_uint2(*(unsigned*)&h0, *(unsigned*)&h1);
    }
}

// ---------------- k2: scan ---------------------------------------------------
__global__ void __launch_bounds__(1024) scan1_kernel()
{
    __shared__ unsigned wsum[32];
    int t = threadIdx.x;
    int lane = t & 31;
    int wid = t >> 5;
    int i = blockIdx.x * 1024 + t;
    unsigned v = g_hist[i];

    unsigned x = v;
    #pragma unroll
    for (int off = 1; off < 32; off <<= 1) {
        unsigned y = __shfl_up_sync(0xFFFFFFFFu, x, off);
        if (lane >= off) x += y;
    }
    if (lane == 31) wsum[wid] = x;
    __syncthreads();
    if (wid == 0) {
        unsigned w = wsum[lane];
        unsigned ww = w;
        #pragma unroll
        for (int off = 1; off < 32; off <<= 1) {
            unsigned y = __shfl_up_sync(0xFFFFFFFFu, ww, off);
            if (lane >= off) ww += y;
        }
        wsum[lane] = ww - w;
        if (lane == 31) g_blksum[blockIdx.x] = ww;
    }
    __syncthreads();
    g_hist[i] = x + wsum[wid] - v;
}

// ---------------- k3: scatter -------------------------------------------------
__global__ void scatter_kernel(const float* __restrict__ pts,
                               const float* __restrict__ aabb, int n)
{
    __shared__ unsigned blkoff[32];
    int t = threadIdx.x;
    if (t < 32) {
        unsigned v = g_blksum[t];
        unsigned x = v;
        #pragma unroll
        for (int off = 1; off < 32; off <<= 1) {
            unsigned y = __shfl_up_sync(0xFFFFFFFFu, x, off);
            if (t >= off) x += y;
        }
        blkoff[t] = x - v;
    }
    __syncthreads();

    int i = blockIdx.x * blockDim.x + t;
    if (i >= n) return;
    unsigned key = g_key[i];
    unsigned pos = atomicAdd(&g_hist[key], 1u) + blkoff[key >> 10];

    float a0x = aabb[0], a0y = aabb[1], a0z = aabb[2];
    float a1x = aabb[3], a1y = aabb[4], a1z = aabb[5];
    float xs0 = (pts[3 * i + 0] - a0x) * (2.0f / (a1x - a0x)) - 1.0f;
    float xs1 = (pts[3 * i + 1] - a0y) * (2.0f / (a1y - a0y)) - 1.0f;
    float xs2 = (pts[3 * i + 2] - a0z) * (2.0f / (a1z - a0z)) - 1.0f;
    g_spts[pos] = make_float4(xs0, xs1, xs2, __int_as_float(i));
}

__global__ void ident_kernel(const float* __restrict__ pts,
                             const float* __restrict__ aabb, int n)
{
    int i = blockIdx.x * blockDim.x + threadIdx.x;
    if (i >= n) return;
    float a0x = aabb[0], a0y = aabb[1], a0z = aabb[2];
    float a1x = aabb[3], a1y = aabb[4], a1z = aabb[5];
    float xs0 = (pts[3 * i + 0] - a0x) * (2.0f / (a1x - a0x)) - 1.0f;
    float xs1 = (pts[3 * i + 1] - a0y) * (2.0f / (a1y - a0y)) - 1.0f;
    float xs2 = (pts[3 * i + 2] - a0z) * (2.0f / (a1z - a0z)) - 1.0f;
    g_spts[i] = make_float4(xs0, xs1, xs2, __int_as_float(i));
}

// ---------------- fp16 helpers ----------------------------------------------
__device__ __forceinline__ void h8tof8(uint4 u, float* f)
{
    float2 p;
    p = __half22float2(*(const __half2*)&u.x); f[0] = p.x; f[1] = p.y;
    p = __half22float2(*(const __half2*)&u.y); f[2] = p.x; f[3] = p.y;
    p = __half22float2(*(const __half2*)&u.z); f[4] = p.x; f[5] = p.y;
    p = __half22float2(*(const __half2*)&u.w); f[6] = p.x; f[7] = p.y;
}

struct SCtx { const uint4* b; int rs; float wx, wy; };

__device__ __forceinline__ SCtx mkctx(const __half* __restrict__ T, int r,
                                      float u, float v, int c8)
{
    float fr = (float)(r - 1);
    float fx = (u + 1.0f) * 0.5f * fr;
    float fy = (v + 1.0f) * 0.5f * fr;
    float flx = fminf(fmaxf(floorf(fx), 0.0f), (float)(r - 2));
    float fly = fminf(fmaxf(floorf(fy), 0.0f), (float)(r - 2));
    SCtx c;
    c.wx = fx - flx;
    c.wy = fy - fly;
    int ix = (int)flx;
    int iy = (int)fly;
    c.b  = (const uint4*)(T + ((iy * r + ix) << 5)) + c8;
    c.rs = r << 2;
    return c;
}

__device__ __forceinline__ void lerp8(uint4 a00, uint4 a01, uint4 a10, uint4 a11,
                                      float wx, float wy, float* o)
{
    float f00[8], f01[8], f10[8], f11[8];
    h8tof8(a00, f00); h8tof8(a01, f01); h8tof8(a10, f10); h8tof8(a11, f11);
    #pragma unroll
    for (int k = 0; k < 8; k++) {
        float t0 = f00[k] + (f01[k] - f00[k]) * wx;
        float t1 = f10[k] + (f11[k] - f10[k]) * wx;
        o[k] = t0 + (t1 - t0) * wy;
    }
}

// ---------------- k4: field kernel: 8 pts/warp --------------------------------
__global__ void __launch_bounds__(256) field_kernel(
    const float* __restrict__ ks,
    const float* __restrict__ kpb,
    float* __restrict__ out,
    int npts)
{
    int gwarp = (int)((blockIdx.x * blockDim.x + threadIdx.x) >> 5);
    int lane  = threadIdx.x & 31;
    int pslot = lane >> 2;
    int c8    = lane & 3;

    int slot = gwarp * 8 + pslot;
    if (slot >= npts) return;

    float4 sp = __ldg(&g_spts[slot]);
    float xs0 = sp.x, xs1 = sp.y, xs2 = sp.z;
    int pid = __float_as_int(sp.w);

    float* outP = out + (size_t)pid * 128;
    const float4* kpb4 = (const float4*)kpb;

    const int resArr[3] = {128, 256, 512};
    #pragma unroll
    for (int s = 0; s < 3; s++) {
        int r = resArr[s];
        SCtx c0 = mkctx(g_planesTh + c_plane_off[s * 3 + 0], r, xs0, xs1, c8);
        SCtx c1 = mkctx(g_planesTh + c_plane_off[s * 3 + 1], r, xs0, xs2, c8);
        SCtx c2 = mkctx(g_planesTh + c_plane_off[s * 3 + 2], r, xs1, xs2, c8);
        // batch all 12 loads (MLP=12) before converting
        uint4 a00 = __ldg(c0.b),            a01 = __ldg(c0.b + 4);
        uint4 a10 = __ldg(c0.b + c0.rs),    a11 = __ldg(c0.b + c0.rs + 4);
        uint4 b00 = __ldg(c1.b),            b01 = __ldg(c1.b + 4);
        uint4 b10 = __ldg(c1.b + c1.rs),    b11 = __ldg(c1.b + c1.rs + 4);
        uint4 d00 = __ldg(c2.b),            d01 = __ldg(c2.b + 4);
        uint4 d10 = __ldg(c2.b + c2.rs),    d11 = __ldg(c2.b + c2.rs + 4);
        float f0[8], f1[8], f2[8];
        lerp8(a00, a01, a10, a11, c0.wx, c0.wy, f0);
        lerp8(b00, b01, b10, b11, c1.wx, c1.wy, f1);
        lerp8(d00, d01, d10, d11, c2.wx, c2.wy, f2);
        float4 bb0 = __ldg(kpb4 + s * 8 + c8 * 2);
        float4 bb1 = __ldg(kpb4 + s * 8 + c8 * 2 + 1);
        float4 o0, o1;
        o0.x = f0[0] * f1[0] * f2[0] + bb0.x;
        o0.y = f0[1] * f1[1] * f2[1] + bb0.y;
        o0.z = f0[2] * f1[2] * f2[2] + bb0.z;
        o0.w = f0[3] * f1[3] * f2[3] + bb0.w;
        o1.x = f0[4] * f1[4] * f2[4] + bb1.x;
        o1.y = f0[5] * f1[5] * f2[5] + bb1.y;
        o1.z = f0[6] * f1[6] * f2[6] + bb1.z;
        o1.w = f0[7] * f1[7] * f2[7] + bb1.w;
        float* op = outP + s * 32 + (c8 << 3);
        __stcs((float4*)op, o0);           // streaming: don't pollute L2
        __stcs((float4*)(op + 4), o1);
    }

    // ---- RBF features over 64^3 grid on [-1,1]
    const float interval = 2.0f / (float)(NSIDE - 1);
    float c0f = fminf(fmaxf(floorf((xs0 + 1.0f) / interval), 0.0f), (float)(NSIDE - 2));
    float c1f = fminf(fmaxf(floorf((xs1 + 1.0f) / interval), 0.0f), (float)(NSIDE - 2));
    float c2f = fminf(fmaxf(floorf((xs2 + 1.0f) / interval), 0.0f), (float)(NSIDE - 2));
    int ci0 = (int)c0f, ci1 = (int)c1f, ci2 = (int)c2f;

    // batch all index computation + loads
    int idxA[8];
    float d2A[8];
    #pragma unroll
    for (int k = 0; k < 8; k++) {
        int i0 = ci0 + ((k >> 2) & 1);
        int i1 = ci1 + ((k >> 1) & 1);
        int i2 = ci2 + (k & 1);
        idxA[k] = (i0 * NSIDE + i1) * NSIDE + i2;
        float d0 = xs0 - (-1.0f + (float)i0 * interval);
        float d1 = xs1 - (-1.0f + (float)i1 * interval);
        float d2 = xs2 - (-1.0f + (float)i2 * interval);
        d2A[k] = d0 * d0 + d1 * d1 + d2 * d2;
    }
    float svA[8];
    uint4 cuA[8];
    #pragma unroll
    for (int k = 0; k < 8; k++) {
        svA[k] = __ldg(&ks[idxA[k]]);
        cuA[k] = __ldg((const uint4*)(g_lc0h + (idxA[k] << 5)) + c8);
    }

    float acc[8] = {0.f, 0.f, 0.f, 0.f, 0.f, 0.f, 0.f, 0.f};
    float wsum = 0.0f;
    #pragma unroll
    for (int k = 0; k < 8; k++) {
        float phi = 1.0f / (1.0f + d2A[k] * svA[k] * svA[k]);
        wsum += phi;
        float code[8];
        h8tof8(cuA[k], code);
        #pragma unroll
        for (int j = 0; j < 8; j++) acc[j] += phi * code[j];
    }
    float inv = 1.0f / (wsum + 1e-8f);
    float4 bb0 = __ldg(kpb4 + 24 + c8 * 2);
    float4 bb1 = __ldg(kpb4 + 24 + c8 * 2 + 1);
    float4 o0, o1;
    o0.x = acc[0] * inv + bb0.x;
    o0.y = acc[1] * inv + bb0.y;
    o0.z = acc[2] * inv + bb0.z;
    o0.w = acc[3] * inv + bb0.w;
    o1.x = acc[4] * inv + bb1.x;
    o1.y = acc[5] * inv + bb1.y;
    o1.z = acc[6] * inv + bb1.z;
    o1.w = acc[7] * inv + bb1.w;
    float* op = outP + 96 + (c8 << 3);
    __stcs((float4*)op, o0);
    __stcs((float4*)(op + 4), o1);
}

// ------------------------------ launcher ------------------------------------
extern "C" void kernel_launch(void* const* d_in, const int* in_sizes, int n_in,
                              void* d_out, int out_size)
{
    const float* pts  = (const float*)d_in[0];
    const float* aabb = (const float*)d_in[1];
    const float* lc0  = (const float*)d_in[11];
    const float* ks   = (const float*)d_in[12];
    const float* kpb  = (const float*)d_in[13];
    float* out = (float*)d_out;

    int npts = in_sizes[0] / 3;

    // zero histogram via memset node (not a kernel launch)
    void* histPtr = nullptr;
    cudaGetSymbolAddress(&histPtr, g_hist);
    cudaMemsetAsync(histPtr, 0, NBUCK * sizeof(unsigned));

    PrepArgs a;
    for (int i = 0; i < 9; i++) a.p[i] = (const float*)d_in[2 + i];
    a.lc0 = lc0;
    a.pts = pts;
    a.aabb = aabb;
    a.n = npts;

    if (npts <= MAXN) {
        int histBlocks = (npts + 255) / 256;
        prep_kernel<<<16256 + histBlocks, 256>>>(a);   // transpose+lc0+hist
        scan1_kernel<<<32, 1024>>>();
        scatter_kernel<<<(npts + 255) / 256, 256>>>(pts, aabb, npts);
    } else {
        a.n = 0;
        prep_kernel<<<16256, 256>>>(a);
        ident_kernel<<<(npts + 255) / 256, 256>>>(pts, aabb, npts);
    }

    int blocks = (npts + 63) / 64;    // 8 pts/warp * 8 warps
    field_kernel<<<blocks, 256>>>(ks, kpb, out, npts);
}